// round 14
// baseline (speedup 1.0000x reference)
#include <cuda_runtime.h>
#include <cstdint>

// out[b, f] = (medians[f] > 0 && inputs[b, f] >= medians[f]) ? 1.0f : 0.0f
// inputs: 8192 x 4096 fp32 (134 MB streamed), medians: 4096 fp32,
// output: float32 (134 MB streamed).
//
// R14 = R9/R13 winning configuration (45.1us, ~7.17 TB/s effective, ~90% of
// spec) with ONE change: stores use __stwt (st.global.wt, write-through)
// instead of __stcs. Same total DRAM traffic, but no dirty L2 lines -> no
// eviction writeback bursts stealing bandwidth from the next graph replay's
// reads; stores stream to DRAM in-window.
//   - Column-tiled: 256-thread block owns 256 consecutive float4 columns
//     (quarter row) -> every warp access is 512 contiguous bytes.
//   - Median float4 register-resident per thread.
//   - All 8 rows' loads batched (__ldcs) before any store.

#define ROW4   1024   // float4 per row (4096 floats)
#define COLS4  256    // float4 columns per block (= blockDim.x)
#define RGRP   8      // rows per block
#define NROWS  8192

__device__ __forceinline__ float4 cmp4(float4 a, float4 m) {
    float4 r;
    r.x = (m.x > 0.0f && a.x >= m.x) ? 1.0f : 0.0f;
    r.y = (m.y > 0.0f && a.y >= m.y) ? 1.0f : 0.0f;
    r.z = (m.z > 0.0f && a.z >= m.z) ? 1.0f : 0.0f;
    r.w = (m.w > 0.0f && a.w >= m.w) ? 1.0f : 0.0f;
    return r;
}

__global__ void __launch_bounds__(COLS4)
binarize_kernel(const float4* __restrict__ in,
                const float4* __restrict__ med,
                float4* __restrict__ out) {
    // 4 column-groups per row; row-groups in the upper grid bits.
    unsigned cg   = blockIdx.x & 3u;           // quarter of the row
    unsigned rg   = blockIdx.x >> 2;           // row group
    unsigned col4 = cg * COLS4 + threadIdx.x;
    size_t   base = (size_t)rg * RGRP * ROW4 + col4;

    const float4 m = med[col4];                // register-resident across rows

    // Rows 0..3 in flight.
    float4 a0 = __ldcs(&in[base + 0 * ROW4]);
    float4 a1 = __ldcs(&in[base + 1 * ROW4]);
    float4 a2 = __ldcs(&in[base + 2 * ROW4]);
    float4 a3 = __ldcs(&in[base + 3 * ROW4]);

    // Rows 4..7 loaded BEFORE storing rows 0..3.
    size_t nb = base + 4 * (size_t)ROW4;
    float4 b0 = __ldcs(&in[nb + 0 * ROW4]);
    float4 b1 = __ldcs(&in[nb + 1 * ROW4]);
    float4 b2 = __ldcs(&in[nb + 2 * ROW4]);
    float4 b3 = __ldcs(&in[nb + 3 * ROW4]);

    __stwt(&out[base + 0 * ROW4], cmp4(a0, m));
    __stwt(&out[base + 1 * ROW4], cmp4(a1, m));
    __stwt(&out[base + 2 * ROW4], cmp4(a2, m));
    __stwt(&out[base + 3 * ROW4], cmp4(a3, m));

    __stwt(&out[nb + 0 * ROW4], cmp4(b0, m));
    __stwt(&out[nb + 1 * ROW4], cmp4(b1, m));
    __stwt(&out[nb + 2 * ROW4], cmp4(b2, m));
    __stwt(&out[nb + 3 * ROW4], cmp4(b3, m));
}

extern "C" void kernel_launch(void* const* d_in, const int* in_sizes, int n_in,
                              void* d_out, int out_size) {
    // Defensive: larger tensor = inputs, smaller = medians.
    int ii = 0, mi = 1;
    if (n_in >= 2 && in_sizes[1] > in_sizes[0]) { ii = 1; mi = 0; }

    const float4* in  = (const float4*)d_in[ii];
    const float4* med = (const float4*)d_in[mi];
    float4* out = (float4*)d_out;

    // 4 col-groups x (8192 / RGRP) row-groups = 4096 blocks of 256 threads.
    unsigned grid = 4u * (NROWS / RGRP);
    binarize_kernel<<<grid, COLS4>>>(in, med, out);
}

// round 16
// speedup vs baseline: 1.0096x; 1.0096x over previous
#include <cuda_runtime.h>
#include <cstdint>

// out[b, f] = (medians[f] > 0 && inputs[b, f] >= medians[f]) ? 1.0f : 0.0f
// inputs: 8192 x 4096 fp32 (134 MB streamed), medians: 4096 fp32,
// output: float32 (134 MB streamed).
//
// R14 = R9/R13 winning configuration (45.1us, ~7.17 TB/s effective, ~90% of
// spec) with ONE change: stores use __stwt (st.global.wt, write-through)
// instead of __stcs. Same total DRAM traffic, but no dirty L2 lines -> no
// eviction writeback bursts stealing bandwidth from the next graph replay's
// reads; stores stream to DRAM in-window.
//   - Column-tiled: 256-thread block owns 256 consecutive float4 columns
//     (quarter row) -> every warp access is 512 contiguous bytes.
//   - Median float4 register-resident per thread.
//   - All 8 rows' loads batched (__ldcs) before any store.

#define ROW4   1024   // float4 per row (4096 floats)
#define COLS4  256    // float4 columns per block (= blockDim.x)
#define RGRP   8      // rows per block
#define NROWS  8192

__device__ __forceinline__ float4 cmp4(float4 a, float4 m) {
    float4 r;
    r.x = (m.x > 0.0f && a.x >= m.x) ? 1.0f : 0.0f;
    r.y = (m.y > 0.0f && a.y >= m.y) ? 1.0f : 0.0f;
    r.z = (m.z > 0.0f && a.z >= m.z) ? 1.0f : 0.0f;
    r.w = (m.w > 0.0f && a.w >= m.w) ? 1.0f : 0.0f;
    return r;
}

__global__ void __launch_bounds__(COLS4)
binarize_kernel(const float4* __restrict__ in,
                const float4* __restrict__ med,
                float4* __restrict__ out) {
    // 4 column-groups per row; row-groups in the upper grid bits.
    unsigned cg   = blockIdx.x & 3u;           // quarter of the row
    unsigned rg   = blockIdx.x >> 2;           // row group
    unsigned col4 = cg * COLS4 + threadIdx.x;
    size_t   base = (size_t)rg * RGRP * ROW4 + col4;

    const float4 m = med[col4];                // register-resident across rows

    // Rows 0..3 in flight.
    float4 a0 = __ldcs(&in[base + 0 * ROW4]);
    float4 a1 = __ldcs(&in[base + 1 * ROW4]);
    float4 a2 = __ldcs(&in[base + 2 * ROW4]);
    float4 a3 = __ldcs(&in[base + 3 * ROW4]);

    // Rows 4..7 loaded BEFORE storing rows 0..3.
    size_t nb = base + 4 * (size_t)ROW4;
    float4 b0 = __ldcs(&in[nb + 0 * ROW4]);
    float4 b1 = __ldcs(&in[nb + 1 * ROW4]);
    float4 b2 = __ldcs(&in[nb + 2 * ROW4]);
    float4 b3 = __ldcs(&in[nb + 3 * ROW4]);

    __stwt(&out[base + 0 * ROW4], cmp4(a0, m));
    __stwt(&out[base + 1 * ROW4], cmp4(a1, m));
    __stwt(&out[base + 2 * ROW4], cmp4(a2, m));
    __stwt(&out[base + 3 * ROW4], cmp4(a3, m));

    __stwt(&out[nb + 0 * ROW4], cmp4(b0, m));
    __stwt(&out[nb + 1 * ROW4], cmp4(b1, m));
    __stwt(&out[nb + 2 * ROW4], cmp4(b2, m));
    __stwt(&out[nb + 3 * ROW4], cmp4(b3, m));
}

extern "C" void kernel_launch(void* const* d_in, const int* in_sizes, int n_in,
                              void* d_out, int out_size) {
    // Defensive: larger tensor = inputs, smaller = medians.
    int ii = 0, mi = 1;
    if (n_in >= 2 && in_sizes[1] > in_sizes[0]) { ii = 1; mi = 0; }

    const float4* in  = (const float4*)d_in[ii];
    const float4* med = (const float4*)d_in[mi];
    float4* out = (float4*)d_out;

    // 4 col-groups x (8192 / RGRP) row-groups = 4096 blocks of 256 threads.
    unsigned grid = 4u * (NROWS / RGRP);
    binarize_kernel<<<grid, COLS4>>>(in, med, out);
}